// round 11
// baseline (speedup 1.0000x reference)
#include <cuda_runtime.h>
#include <cuda_fp16.h>
#include <cuda_bf16.h>

// Problem constants
#define Bn 4
#define Cn 64
#define Hn 96
#define Wn 96
#define PLANE (Hn*Wn)            // 9216
#define NPLANES (Bn*Cn)          // 256
#define NTOT (NPLANES*PLANE)     // 2359296
#define CNT_PER_CH (Bn*PLANE)    // 36864
#define BN_EPS 1e-5f
#define NPART 36                 // partial sums per channel: Bn * (3x3 blocks)

// Scratch (__device__ globals; allocation-free rule)
__device__ float    g_psum[Cn * NPART];
__device__ float    g_psq [Cn * NPART];
__device__ float    g_bn_scl[Cn];        // scl per channel
__device__ float    g_bn_sh [Cn];        // sh  per channel
__device__ unsigned g_cnt [Cn];          // arrival counters (reset each launch)
__device__ unsigned g_done[Cn];          // monotone completion sequence

__device__ __forceinline__ float silu_f(float x) {
    return __fdividef(x, 1.0f + __expf(-x));
}

// ---------------------------------------------------------------------------
// Single kernel: KAN depthwise conv (base folded into spline table) ->
// race-free per-channel partials -> channel-scoped completion wait ->
// BN + ReLU applied from registers, direct store to out.
// grid = (3, 3, 256) with blockIdx.z = 4*channel + batch so each channel's
// 36 blocks are consecutive in schedule order (co-resident -> bounded wait).
// ---------------------------------------------------------------------------
__global__ __launch_bounds__(256)
void kan_fused_kernel(const float* __restrict__ x,
                      const float* __restrict__ base_weight,    // (9)
                      const float* __restrict__ spline_weight,  // (9,8)
                      const float* __restrict__ spline_scaler,  // (9)
                      const float* __restrict__ gamma,
                      const float* __restrict__ beta,
                      float* __restrict__ out)
{
    __shared__ float2   s_t[34 * 35];      // (u | silu, coef-row byte offset)
    __shared__ uint2    s_coef[12 * 9];    // half2(c0,c1), half2(c2,c3)
    __shared__ float    s_rs[8], s_rq[8];
    __shared__ float    s_scl, s_sh;
    __shared__ unsigned s_e0;

    const int tid  = threadIdx.x;
    const int z    = blockIdx.z;
    const int c    = z >> 2;               // channel
    const int b    = z & 3;                // batch
    const int plane = b * Cn + c;
    const int ty0  = blockIdx.y * 32;
    const int tx0  = blockIdx.x * 32;

    // snapshot the completion sequence BEFORE publishing our partial
    if (tid == 0) s_e0 = *(volatile unsigned*)&g_done[c];

    // ---- build coefficient table: uniform cubic B-spline (closed form)
    //      + Hermite cubic of bw[k]*silu(x).  Sentinel row m=11: poly(u)=bw[k]*u
    //      with u := silu(x) for out-of-range x.
    if (tid < 108) {
        const int m = tid / 9, k = tid % 9;
        const float bwk = base_weight[k];
        float c0, c1, c2, c3;
        if (m < 11) {
            c0 = c1 = c2 = c3 = 0.f;
            const float F[4][4] = {
                {1.f, -3.f,  3.f, -1.f},
                {4.f,  0.f, -6.f,  3.f},
                {1.f,  3.f,  3.f, -3.f},
                {0.f,  0.f,  0.f,  1.f}
            };
            const float sc = spline_scaler[k] * (1.0f / 6.0f);
            #pragma unroll
            for (int r = 0; r < 4; r++) {
                int j = m - 3 + r;
                if (j >= 0 && j < 8) {
                    float w = spline_weight[k * 8 + j] * sc;
                    c0 += w * F[r][0]; c1 += w * F[r][1];
                    c2 += w * F[r][2]; c3 += w * F[r][3];
                }
            }
            const float x0 = -2.2f + 0.4f * (float)m;
            const float x1 = x0 + 0.4f;
            const float f0 = silu_f(x0), f1 = silu_f(x1);
            const float sg0 = 1.0f / (1.0f + __expf(-x0));
            const float sg1 = 1.0f / (1.0f + __expf(-x1));
            const float d0 = 0.4f * sg0 * (1.0f + x0 * (1.0f - sg0));
            const float d1 = 0.4f * sg1 * (1.0f + x1 * (1.0f - sg1));
            c0 += bwk * f0;
            c1 += bwk * d0;
            c2 += bwk * (3.0f * (f1 - f0) - 2.0f * d0 - d1);
            c3 += bwk * (2.0f * (f0 - f1) + d0 + d1);
        } else {
            c0 = 0.f; c1 = bwk; c2 = 0.f; c3 = 0.f;
        }
        __half2 h01 = __floats2half2_rn(c0, c1);
        __half2 h23 = __floats2half2_rn(c2, c3);
        uint2 w;
        w.x = *reinterpret_cast<unsigned*>(&h01);
        w.y = *reinterpret_cast<unsigned*>(&h23);
        s_coef[m * 9 + k] = w;
    }

    // ---- load + transform halo tile (34x34), zero-padded outside plane ----
    const float* xp = x + plane * PLANE;
    for (int i = tid; i < 34 * 34; i += 256) {
        int hy = i / 34, hx = i % 34;
        int gy = ty0 + hy - 1, gx = tx0 + hx - 1;
        float v = (gy >= 0 && gy < Hn && gx >= 0 && gx < Wn) ? xp[gy * Wn + gx] : 0.0f;
        float mu = (v + 2.2f) * 2.5f;
        float2 e;
        if (mu >= 0.0f && mu < 11.0f) {
            int m = (int)mu;
            e = make_float2(mu - (float)m, __int_as_float(m * 72));
        } else {
            e = make_float2(silu_f(v), __int_as_float(11 * 72));
        }
        s_t[hy * 35 + hx] = e;
    }
    __syncthreads();

    // ---- compute 32x32 outputs (4 strided rows per thread) ----
    const int tx  = tid & 31;
    const int tyb = tid >> 5;
    float lsum = 0.f, lsq = 0.f;
    float yv[4];
    const char* cbase = (const char*)s_coef;

    #pragma unroll
    for (int r = 0; r < 4; r++) {
        const int oy = tyb + r * 8;
        float acc = 0.f;
        #pragma unroll
        for (int dy = 0; dy < 3; dy++) {
            #pragma unroll
            for (int dx = 0; dx < 3; dx++) {
                const int k = dy * 3 + dx;
                float2 t = s_t[(oy + dy) * 35 + (tx + dx)];
                uint2  cw = *(const uint2*)(cbase + __float_as_int(t.y) + k * 8);
                float2 c01 = __half22float2(*reinterpret_cast<__half2*>(&cw.x));
                float2 c23 = __half22float2(*reinterpret_cast<__half2*>(&cw.y));
                acc += fmaf(t.x, fmaf(t.x, fmaf(t.x, c23.y, c23.x), c01.y), c01.x);
            }
        }
        yv[r] = acc;
        lsum += acc;
        lsq  = fmaf(acc, acc, lsq);
    }

    // ---- block reduction -> race-free partial slot ----
    #pragma unroll
    for (int o = 16; o > 0; o >>= 1) {
        lsum += __shfl_down_sync(0xffffffffu, lsum, o);
        lsq  += __shfl_down_sync(0xffffffffu, lsq,  o);
    }
    if (tx == 0) { s_rs[tyb] = lsum; s_rq[tyb] = lsq; }
    __syncthreads();

    // ---- publish partial; 36th arrival computes (scl, sh); others wait ----
    if (tid == 0) {
        float s = 0.f, q = 0.f;
        #pragma unroll
        for (int i = 0; i < 8; i++) { s += s_rs[i]; q += s_rq[i]; }
        const int slot = c * NPART + b * 9 + blockIdx.y * 3 + blockIdx.x;
        g_psum[slot] = s;
        g_psq [slot] = q;
        __threadfence();
        unsigned old = atomicAdd(&g_cnt[c], 1u);
        if (old == NPART - 1) {
            atomicExch(&g_cnt[c], 0u);               // reset for next replay
            float ts = 0.f, tq = 0.f;
            #pragma unroll 4
            for (int j = 0; j < NPART; j++) {
                ts += __ldcg(&g_psum[c * NPART + j]);
                tq += __ldcg(&g_psq [c * NPART + j]);
            }
            const float invN = 1.0f / (float)CNT_PER_CH;
            float mean = ts * invN;
            float var  = tq * invN - mean * mean;
            float scl  = rsqrtf(var + BN_EPS) * gamma[c];
            g_bn_scl[c] = scl;
            g_bn_sh [c] = fmaf(-mean, scl, beta[c]);
            __threadfence();
            atomicAdd(&g_done[c], 1u);               // signal (monotone)
        }
        // wait for this channel's stats (snapshot taken pre-publish)
        const unsigned e0 = s_e0;
        while (*(volatile unsigned*)&g_done[c] == e0) __nanosleep(64);
        __threadfence();
        s_scl = *(volatile float*)&g_bn_scl[c];
        s_sh  = *(volatile float*)&g_bn_sh [c];
    }
    __syncthreads();

    // ---- BN + ReLU from registers, direct store ----
    const float scl = s_scl, sh = s_sh;
    float* op = out + plane * PLANE + tx0 + tx;
    #pragma unroll
    for (int r = 0; r < 4; r++) {
        const int oy = tyb + r * 8;
        op[(ty0 + oy) * Wn] = fmaxf(fmaf(yv[r], scl, sh), 0.0f);
    }
}

// ---------------------------------------------------------------------------
extern "C" void kernel_launch(void* const* d_in, const int* in_sizes, int n_in,
                              void* d_out, int out_size)
{
    const float* x             = (const float*)d_in[0];
    const float* base_weight   = (const float*)d_in[1];
    const float* spline_weight = (const float*)d_in[2];
    const float* spline_scaler = (const float*)d_in[3];
    const float* bn_gamma      = (const float*)d_in[4];
    const float* bn_beta       = (const float*)d_in[5];
    float* out                 = (float*)d_out;

    dim3 grid(3, 3, NPLANES);
    kan_fused_kernel<<<grid, 256>>>(x, base_weight, spline_weight, spline_scaler,
                                    bn_gamma, bn_beta, out);
}

// round 12
// speedup vs baseline: 1.4321x; 1.4321x over previous
#include <cuda_runtime.h>
#include <cuda_fp16.h>
#include <cuda_bf16.h>

// Problem constants
#define Bn 4
#define Cn 64
#define Hn 96
#define Wn 96
#define PLANE (Hn*Wn)            // 9216
#define NPLANES (Bn*Cn)          // 256
#define NTOT (NPLANES*PLANE)     // 2359296
#define CNT_PER_CH (Bn*PLANE)    // 36864
#define BN_EPS 1e-5f
#define NPART 36                 // partial sums per channel: Bn * (3x3 blocks)

// Scratch (__device__ globals; allocation-free rule)
__device__ float g_y[NTOT];
__device__ float g_psum[Cn * NPART];
__device__ float g_psq [Cn * NPART];

// ---------------------------------------------------------------------------
// Kernel 1: fused KAN depthwise conv + race-free per-channel partial sums
// grid = (3, 3, 256 planes), block = 256 threads (32 x 8), 4 rows/thread.
// (Exact R7 structure — fastest measured conv core.)
// ---------------------------------------------------------------------------
__global__ __launch_bounds__(256)
void kan_conv_kernel(const float* __restrict__ x,
                     const float* __restrict__ base_weight,    // (9)
                     const float* __restrict__ spline_weight,  // (9,8)
                     const float* __restrict__ spline_scaler)  // (9)
{
    __shared__ float2 s_su[34 * 35];       // (silu, u) tile with halo, pitch 35
    __shared__ int    s_mo[34 * 35];       // coef row byte offset = m * 72
    __shared__ uint2  s_coef[12 * 9];      // half2(c0,c1), half2(c2,c3)
    __shared__ float  s_bw[9];
    __shared__ float  s_rs[8], s_rq[8];

    const int tid   = threadIdx.x;
    const int plane = blockIdx.z;
    const int ty0   = blockIdx.y * 32;
    const int tx0   = blockIdx.x * 32;

    // ---- build coefficient table (uniform cubic B-spline, closed form) ----
    if (tid < 108) {
        const int m = tid / 9, k = tid % 9;
        float c0 = 0.f, c1 = 0.f, c2 = 0.f, c3 = 0.f;
        if (m < 11) {
            const float F[4][4] = {
                {1.f, -3.f,  3.f, -1.f},   // N_{m-3}
                {4.f,  0.f, -6.f,  3.f},   // N_{m-2}
                {1.f,  3.f,  3.f, -3.f},   // N_{m-1}
                {0.f,  0.f,  0.f,  1.f}    // N_{m}
            };
            const float sc = spline_scaler[k];
            #pragma unroll
            for (int r = 0; r < 4; r++) {
                int j = m - 3 + r;
                if (j >= 0 && j < 8) {
                    float w = spline_weight[k * 8 + j] * sc;
                    c0 += w * F[r][0]; c1 += w * F[r][1];
                    c2 += w * F[r][2]; c3 += w * F[r][3];
                }
            }
        }
        const float inv6 = 1.0f / 6.0f;
        __half2 h01 = __floats2half2_rn(c0 * inv6, c1 * inv6);
        __half2 h23 = __floats2half2_rn(c2 * inv6, c3 * inv6);
        uint2 w;
        w.x = *reinterpret_cast<unsigned*>(&h01);
        w.y = *reinterpret_cast<unsigned*>(&h23);
        s_coef[m * 9 + k] = w;
    }
    if (tid < 9) s_bw[tid] = base_weight[tid];

    // ---- load + transform + decode halo tile (34x34) ----
    const float* xp = x + plane * PLANE;
    for (int i = tid; i < 34 * 34; i += 256) {
        int hy = i / 34, hx = i % 34;
        int gy = ty0 + hy - 1, gx = tx0 + hx - 1;
        float v = (gy >= 0 && gy < Hn && gx >= 0 && gx < Wn) ? xp[gy * Wn + gx] : 0.0f;
        float s  = __fdividef(v, 1.0f + __expf(-v));   // silu
        float mu = (v + 2.2f) * 2.5f;                  // (x - t0)/h
        if (!(mu >= 0.0f && mu < 11.0f)) mu = 11.0f;   // sentinel -> zero row
        int   m = (int)mu;
        float u = mu - (float)m;
        const int idx = hy * 35 + hx;
        s_su[idx] = make_float2(s, u);
        s_mo[idx] = m * 72;                            // row m of s_coef (9 * 8B)
    }
    __syncthreads();

    // ---- compute 32x32 outputs (4 strided rows per thread) ----
    const int tx  = tid & 31;
    const int tyb = tid >> 5;
    float lsum = 0.f, lsq = 0.f;
    const char* cbase = (const char*)s_coef;

    #pragma unroll
    for (int r = 0; r < 4; r++) {
        const int oy = tyb + r * 8;
        float acc = 0.f;
        #pragma unroll
        for (int dy = 0; dy < 3; dy++) {
            #pragma unroll
            for (int dx = 0; dx < 3; dx++) {
                const int k   = dy * 3 + dx;
                const int idx = (oy + dy) * 35 + (tx + dx);
                float2 t  = s_su[idx];
                int    mo = s_mo[idx];
                uint2  cw = *(const uint2*)(cbase + mo + k * 8);
                float2 c01 = __half22float2(*reinterpret_cast<__half2*>(&cw.x));
                float2 c23 = __half22float2(*reinterpret_cast<__half2*>(&cw.y));
                float poly = fmaf(t.y, fmaf(t.y, fmaf(t.y, c23.y, c23.x), c01.y), c01.x);
                acc += poly + s_bw[k] * t.x;
            }
        }
        g_y[plane * PLANE + (ty0 + oy) * Wn + (tx0 + tx)] = acc;
        lsum += acc;
        lsq  = fmaf(acc, acc, lsq);
    }

    // ---- block reduction -> race-free partial slot ----
    #pragma unroll
    for (int o = 16; o > 0; o >>= 1) {
        lsum += __shfl_down_sync(0xffffffffu, lsum, o);
        lsq  += __shfl_down_sync(0xffffffffu, lsq,  o);
    }
    if (tx == 0) { s_rs[tyb] = lsum; s_rq[tyb] = lsq; }
    __syncthreads();
    if (tid == 0) {
        float s = 0.f, q = 0.f;
        #pragma unroll
        for (int i = 0; i < 8; i++) { s += s_rs[i]; q += s_rq[i]; }
        const int c = plane & (Cn - 1);
        const int b = plane >> 6;
        const int slot = c * NPART + b * 9 + blockIdx.y * 3 + blockIdx.x;
        g_psum[slot] = s;
        g_psq [slot] = q;
    }

    // PDL: this block's dependent memory work is done — allow secondary launch
    cudaTriggerProgrammaticLaunchCompletion();
}

// ---------------------------------------------------------------------------
// Kernel 2: BatchNorm (batch stats from partials) + ReLU
// grid = (3, 256 planes), block = 256; 3 float4 per thread; per-warp
// redundant butterfly stats.  Launched with PDL: ramps up while conv drains,
// then waits on the grid dependency before touching conv outputs.
// ---------------------------------------------------------------------------
__global__ __launch_bounds__(256)
void bn_relu_kernel(const float* __restrict__ gamma,
                    const float* __restrict__ beta,
                    float* __restrict__ out)
{
    const int plane = blockIdx.y;
    const int c     = plane & (Cn - 1);
    const int tid   = threadIdx.x;
    const int lane  = tid & 31;
    const int base  = plane * (PLANE / 4) + blockIdx.x * 768 + tid;
    const float gc  = gamma[c];              // independent of conv — prefetch
    const float bc  = beta[c];

    // wait until conv's memory is visible
    cudaGridDependencySynchronize();

    // start the stats chain FIRST (it is the critical path)
    float s = g_psum[c * NPART + lane % NPART];
    float q = g_psq [c * NPART + lane % NPART];

    // then issue the 3 independent data loads
    float4 v0 = reinterpret_cast<const float4*>(g_y)[base];
    float4 v1 = reinterpret_cast<const float4*>(g_y)[base + 256];
    float4 v2 = reinterpret_cast<const float4*>(g_y)[base + 512];

    if (lane < NPART - 32) {
        s += g_psum[c * NPART + lane + 32];
        q += g_psq [c * NPART + lane + 32];
    }
    #pragma unroll
    for (int o = 16; o > 0; o >>= 1) {
        s += __shfl_xor_sync(0xffffffffu, s, o);
        q += __shfl_xor_sync(0xffffffffu, q, o);
    }

    const float invN = 1.0f / (float)CNT_PER_CH;
    float mean = s * invN;
    float var  = q * invN - mean * mean;
    float scl  = rsqrtf(var + BN_EPS) * gc;
    float sh   = fmaf(-mean, scl, bc);

    float4 o0, o1, o2;
    o0.x = fmaxf(fmaf(v0.x, scl, sh), 0.0f);
    o0.y = fmaxf(fmaf(v0.y, scl, sh), 0.0f);
    o0.z = fmaxf(fmaf(v0.z, scl, sh), 0.0f);
    o0.w = fmaxf(fmaf(v0.w, scl, sh), 0.0f);
    o1.x = fmaxf(fmaf(v1.x, scl, sh), 0.0f);
    o1.y = fmaxf(fmaf(v1.y, scl, sh), 0.0f);
    o1.z = fmaxf(fmaf(v1.z, scl, sh), 0.0f);
    o1.w = fmaxf(fmaf(v1.w, scl, sh), 0.0f);
    o2.x = fmaxf(fmaf(v2.x, scl, sh), 0.0f);
    o2.y = fmaxf(fmaf(v2.y, scl, sh), 0.0f);
    o2.z = fmaxf(fmaf(v2.z, scl, sh), 0.0f);
    o2.w = fmaxf(fmaf(v2.w, scl, sh), 0.0f);
    reinterpret_cast<float4*>(out)[base]       = o0;
    reinterpret_cast<float4*>(out)[base + 256] = o1;
    reinterpret_cast<float4*>(out)[base + 512] = o2;
}

// ---------------------------------------------------------------------------
extern "C" void kernel_launch(void* const* d_in, const int* in_sizes, int n_in,
                              void* d_out, int out_size)
{
    const float* x             = (const float*)d_in[0];
    const float* base_weight   = (const float*)d_in[1];
    const float* spline_weight = (const float*)d_in[2];
    const float* spline_scaler = (const float*)d_in[3];
    const float* bn_gamma      = (const float*)d_in[4];
    const float* bn_beta       = (const float*)d_in[5];
    float* out                 = (float*)d_out;

    dim3 grid(3, 3, NPLANES);
    kan_conv_kernel<<<grid, 256>>>(x, base_weight, spline_weight, spline_scaler);

    // bn with Programmatic Dependent Launch: overlaps its ramp with conv tail
    cudaLaunchConfig_t cfg = {};
    cfg.gridDim  = dim3(3, NPLANES);
    cfg.blockDim = dim3(256);
    cfg.stream   = 0;
    cudaLaunchAttribute attrs[1];
    attrs[0].id = cudaLaunchAttributeProgrammaticStreamSerialization;
    attrs[0].val.programmaticStreamSerializationAllowed = 1;
    cfg.attrs    = attrs;
    cfg.numAttrs = 1;
    cudaLaunchKernelEx(&cfg, bn_relu_kernel, bn_gamma, bn_beta, out);
}